// round 5
// baseline (speedup 1.0000x reference)
#include <cuda_runtime.h>

// ---------------------------------------------------------------------------
// GRU memory updater (TGN-style), fp32, packed-FFMA2 GEMM, row-pair packing.
//
//   gi = msgs @ W_ih^T + b_ih      [B, 384]   (K = 256)
//   gh = h    @ W_hh^T + b_hh      [B, 384]   (K = 128)
//   r = sig(gi_r + gh_r); z = sig(gi_z + gh_z); n = tanh(gi_n + r*gh_n)
//   h_new = (1-z)*n + z*h
//   out_memory = memory with rows[ids] <- h_new ; out_lu = lu with [ids] <- ts
//
// 256 threads, BM=32 rows/block, 2 CTAs/SM. Thread owns ONE column c (plus
// gate siblings c+128, c+256) and 16 rows as 8 packed row-pairs in f32x2
// accumulators. Weights pre-duplicated in smem as (w,w) ull pairs; X/H tiles
// staged k-major so 4 row-pairs load per LDS.128. r/z accumulators shared
// across both GEMM phases (gi+gh pre-summed before sigmoid).
// ---------------------------------------------------------------------------

typedef unsigned long long ull;

#define HDIM      128
#define MSGDIM    256
#define G3        384
#define BM        32
#define KT        16
#define NTHREADS  256

#define WSD_STRIDE 385   // ull stride per k-row of duplicated weights
#define XT_STRIDEF 36    // float stride per k-row of transposed X (16B-aligned)
#define HS_STRIDE  129

#define SMEM_FLOATS (KT*WSD_STRIDE*2 + KT*XT_STRIDEF + BM*HS_STRIDE + 2*BM)
#define SMEM_BYTES  (SMEM_FLOATS * 4)

__device__ __forceinline__ ull pack2(float x, float y) {
    ull r; asm("mov.b64 %0, {%1, %2};" : "=l"(r) : "f"(x), "f"(y)); return r;
}
__device__ __forceinline__ void unpack2(ull v, float& lo, float& hi) {
    asm("mov.b64 {%0, %1}, %2;" : "=f"(lo), "=f"(hi) : "l"(v));
}
// packed dual fp32 FMA: acc = a*b + acc  (2 FMAs / instruction, sm_100+)
__device__ __forceinline__ void fma2(ull& acc, ull a, ull b) {
    asm("fma.rn.f32x2 %0, %1, %2, %0;" : "+l"(acc) : "l"(a), "l"(b));
}
__device__ __forceinline__ float sigmoidf_(float x) {
    return 1.0f / (1.0f + __expf(-x));
}

extern __shared__ float smem_dyn[];

__global__ __launch_bounds__(NTHREADS, 2)
void gru_update_kernel(const float* __restrict__ memory,
                       const int*   __restrict__ ids,
                       const float* __restrict__ msgs,
                       const float* __restrict__ ts,
                       const float* __restrict__ Wih,   // [384, 256] row-major
                       const float* __restrict__ Whh,   // [384, 128] row-major
                       const float* __restrict__ bih,   // [384]
                       const float* __restrict__ bhh,   // [384]
                       float* __restrict__ out_mem,
                       float* __restrict__ out_lu,
                       int B)
{
    ull*   Wsd  = (ull*)smem_dyn;                 // [KT][WSD_STRIDE] (w,w) pairs
    float* XsT  = smem_dyn + KT * WSD_STRIDE * 2; // [KT][XT_STRIDEF] k-major tile
    float* Hs   = XsT + KT * XT_STRIDEF;          // [BM][HS_STRIDE]
    int*   sids = (int*)(Hs + BM * HS_STRIDE);    // [BM]
    float* sts  = (float*)(sids + BM);            // [BM]

    const int t    = threadIdx.x;
    const int c    = t & 127;   // owned column (gates at c, c+128, c+256)
    const int ty   = t >> 7;    // row-half: pairs ty*8 .. ty*8+7
    const int base = blockIdx.x * BM;
    const int lk   = t & (KT - 1);   // fill role: k within chunk
    const int cg   = t >> 4;         // fill role: column group (0..15)

    if (t < BM) {
        int g   = base + t;
        sids[t] = (g < B) ? ids[g] : 0;
        sts[t]  = (g < B) ? ts[g]  : 0.0f;
    }
    __syncthreads();

    // stage gathered memory rows once (phase-B source + epilogue h)
    for (int idx = t; idx < BM * HDIM; idx += NTHREADS) {
        int row = idx >> 7, k = idx & 127;
        Hs[row * HS_STRIDE + k] = memory[(size_t)sids[row] * HDIM + k];
    }
    // ordered before use by the __syncthreads inside the phase loops

    ull accR[8], accZ[8], accN[8], accHN[8];
    #pragma unroll
    for (int i = 0; i < 8; i++) { accR[i] = 0; accZ[i] = 0; accN[i] = 0; accHN[i] = 0; }

    // ---------------- Phase A: gi = X @ Wih^T  (K = 256) ----------------
    for (int k0 = 0; k0 < MSGDIM; k0 += KT) {
        __syncthreads();
        // duplicated weight tile: Wsd[k][col] = (w,w); gmem coalesced along k
        #pragma unroll
        for (int cc = cg; cc < G3; cc += 16) {
            float w = __ldg(&Wih[(size_t)cc * MSGDIM + k0 + lk]);
            Wsd[lk * WSD_STRIDE + cc] = pack2(w, w);
        }
        // transposed X tile: XsT[k][row]; gmem coalesced along k
        #pragma unroll
        for (int j = 0; j < (KT * BM) / NTHREADS; j++) {
            int idx = t + j * NTHREADS;
            int kk = idx & (KT - 1), row = idx >> 4;
            int g = base + row; if (g >= B) g = B - 1;
            XsT[kk * XT_STRIDEF + row] = __ldg(&msgs[(size_t)g * MSGDIM + k0 + kk]);
        }
        __syncthreads();
        #pragma unroll 4
        for (int kk = 0; kk < KT; kk++) {
            const ull* wrow = Wsd + kk * WSD_STRIDE;
            ull wr = wrow[c], wz = wrow[c + 128], wn = wrow[c + 256];
            const ulonglong2* xp =
                (const ulonglong2*)(XsT + kk * XT_STRIDEF) + ty * 4;
            ulonglong2 x01 = xp[0], x23 = xp[1], x45 = xp[2], x67 = xp[3];
            fma2(accR[0], x01.x, wr); fma2(accZ[0], x01.x, wz); fma2(accN[0], x01.x, wn);
            fma2(accR[1], x01.y, wr); fma2(accZ[1], x01.y, wz); fma2(accN[1], x01.y, wn);
            fma2(accR[2], x23.x, wr); fma2(accZ[2], x23.x, wz); fma2(accN[2], x23.x, wn);
            fma2(accR[3], x23.y, wr); fma2(accZ[3], x23.y, wz); fma2(accN[3], x23.y, wn);
            fma2(accR[4], x45.x, wr); fma2(accZ[4], x45.x, wz); fma2(accN[4], x45.x, wn);
            fma2(accR[5], x45.y, wr); fma2(accZ[5], x45.y, wz); fma2(accN[5], x45.y, wn);
            fma2(accR[6], x67.x, wr); fma2(accZ[6], x67.x, wz); fma2(accN[6], x67.x, wn);
            fma2(accR[7], x67.y, wr); fma2(accZ[7], x67.y, wz); fma2(accN[7], x67.y, wn);
        }
    }

    // ---------------- Phase B: gh = H @ Whh^T  (K = 128) ----------------
    // r/z accumulate into the SAME accs (gi+gh pre-summed); n-gate separate.
    for (int k0 = 0; k0 < HDIM; k0 += KT) {
        __syncthreads();
        #pragma unroll
        for (int cc = cg; cc < G3; cc += 16) {
            float w = __ldg(&Whh[(size_t)cc * HDIM + k0 + lk]);
            Wsd[lk * WSD_STRIDE + cc] = pack2(w, w);
        }
        // transposed H tile built from staged Hs (smem -> smem)
        #pragma unroll
        for (int j = 0; j < (KT * BM) / NTHREADS; j++) {
            int idx = t + j * NTHREADS;
            int kk = idx & (KT - 1), row = idx >> 4;
            XsT[kk * XT_STRIDEF + row] = Hs[row * HS_STRIDE + k0 + kk];
        }
        __syncthreads();
        #pragma unroll 4
        for (int kk = 0; kk < KT; kk++) {
            const ull* wrow = Wsd + kk * WSD_STRIDE;
            ull wr = wrow[c], wz = wrow[c + 128], wn = wrow[c + 256];
            const ulonglong2* xp =
                (const ulonglong2*)(XsT + kk * XT_STRIDEF) + ty * 4;
            ulonglong2 x01 = xp[0], x23 = xp[1], x45 = xp[2], x67 = xp[3];
            fma2(accR[0], x01.x, wr); fma2(accZ[0], x01.x, wz); fma2(accHN[0], x01.x, wn);
            fma2(accR[1], x01.y, wr); fma2(accZ[1], x01.y, wz); fma2(accHN[1], x01.y, wn);
            fma2(accR[2], x23.x, wr); fma2(accZ[2], x23.x, wz); fma2(accHN[2], x23.x, wn);
            fma2(accR[3], x23.y, wr); fma2(accZ[3], x23.y, wz); fma2(accHN[3], x23.y, wn);
            fma2(accR[4], x45.x, wr); fma2(accZ[4], x45.x, wz); fma2(accHN[4], x45.x, wn);
            fma2(accR[5], x45.y, wr); fma2(accZ[5], x45.y, wz); fma2(accHN[5], x45.y, wn);
            fma2(accR[6], x67.x, wr); fma2(accZ[6], x67.x, wz); fma2(accHN[6], x67.x, wn);
            fma2(accR[7], x67.y, wr); fma2(accZ[7], x67.y, wz); fma2(accHN[7], x67.y, wn);
        }
    }

    // ---------------- Epilogue: GRU nonlinearity + scatter ----------------
    const float br  = __ldg(&bih[c])       + __ldg(&bhh[c]);
    const float bz  = __ldg(&bih[c + 128]) + __ldg(&bhh[c + 128]);
    const float bin = __ldg(&bih[c + 256]);
    const float bhn = __ldg(&bhh[c + 256]);

    #pragma unroll
    for (int i = 0; i < 8; i++) {
        const int p  = ty * 8 + i;
        const int r0 = 2 * p, r1 = 2 * p + 1;
        float sR0, sR1, sZ0, sZ1, sN0, sN1, sH0, sH1;
        unpack2(accR[i],  sR0, sR1);
        unpack2(accZ[i],  sZ0, sZ1);
        unpack2(accN[i],  sN0, sN1);
        unpack2(accHN[i], sH0, sH1);

        float rr0 = sigmoidf_(sR0 + br);
        float rr1 = sigmoidf_(sR1 + br);
        float zz0 = sigmoidf_(sZ0 + bz);
        float zz1 = sigmoidf_(sZ1 + bz);
        float nn0 = tanhf(sN0 + bin + rr0 * (sH0 + bhn));
        float nn1 = tanhf(sN1 + bin + rr1 * (sH1 + bhn));
        float h0  = Hs[r0 * HS_STRIDE + c];
        float h1  = Hs[r1 * HS_STRIDE + c];

        if (base + r0 < B)
            out_mem[(size_t)sids[r0] * HDIM + c] = (1.0f - zz0) * nn0 + zz0 * h0;
        if (base + r1 < B)
            out_mem[(size_t)sids[r1] * HDIM + c] = (1.0f - zz1) * nn1 + zz1 * h1;
    }

    if (t < BM && base + t < B) out_lu[sids[t]] = sts[t];
}

extern "C" void kernel_launch(void* const* d_in, const int* in_sizes, int n_in,
                              void* d_out, int out_size)
{
    const float* memory      = (const float*)d_in[0];
    const float* last_update = (const float*)d_in[1];
    const int*   ids         = (const int*)  d_in[2];
    const float* msgs        = (const float*)d_in[3];
    const float* ts          = (const float*)d_in[4];
    const float* Wih         = (const float*)d_in[5];
    const float* Whh         = (const float*)d_in[6];
    const float* bih         = (const float*)d_in[7];
    const float* bhh         = (const float*)d_in[8];

    const int n_mem   = in_sizes[0];   // N_NODES * 128
    const int n_nodes = in_sizes[1];   // N_NODES
    const int B       = in_sizes[2];   // number of updates

    float* out_mem = (float*)d_out;
    float* out_lu  = out_mem + (size_t)n_mem;

    // 1) clone memory + last_update into the output (graph-capturable D2D)
    cudaMemcpyAsync(out_mem, memory,      (size_t)n_mem   * sizeof(float),
                    cudaMemcpyDeviceToDevice, 0);
    cudaMemcpyAsync(out_lu,  last_update, (size_t)n_nodes * sizeof(float),
                    cudaMemcpyDeviceToDevice, 0);

    // 2) fused GRU + scatter (same stream -> ordered after the clone)
    cudaFuncSetAttribute(gru_update_kernel,
                         cudaFuncAttributeMaxDynamicSharedMemorySize, SMEM_BYTES);
    dim3 grid((B + BM - 1) / BM);
    gru_update_kernel<<<grid, NTHREADS, SMEM_BYTES>>>(
        memory, ids, msgs, ts, Wih, Whh, bih, bhh, out_mem, out_lu, B);
}

// round 11
// speedup vs baseline: 1.7432x; 1.7432x over previous
#include <cuda_runtime.h>
#include <cuda_bf16.h>
#include <cstdint>

// ---------------------------------------------------------------------------
// GRU memory updater via mma.sync (m16n8k16 bf16) split-precision GEMM.
// tcgen05 is NOT available under this harness (.target sm_103) — use HMMA.
//
//   Fused A = [X(256) | H(128)]  (K = 384), per-CTA M = 64 rows.
//   W fused image: Wf[g][k] = k<256 ? Wih[g][k] : Whh[g][k-256], split into
//   bf16 hi/lo planes by a prep kernel. GEMM per 128-gate block, 3 terms
//   (hi*hi + hi*lo + lo*hi) accumulated in f32.
//   Block order (running state in registers, same thread owns same (row,col)):
//     R : gates [0,128),   K=[0,384) : T = sigmoid(acc + br)
//     HN: gates [256,384), K=[256,384): T = T * (acc + bhn)
//     IN: gates [256,384), K=[0,256) : T = tanh(acc + bin + T)
//     Z : gates [128,256), K=[0,384) : z = sigmoid(acc + bz);
//                                      out = (1-z)*T + z*h  (scatter by ids)
// ---------------------------------------------------------------------------

#define HDIM     128
#define MSGDIM   256
#define G3       384
#define KTOT     384
#define BM       64
#define NTHREADS 256

#define A_STRIDE 392            // bf16 per A row (384 + 8 pad) -> conflict-free
#define W_STRIDE 72             // bf16 per W row (64 + 8 pad)
#define A_BYTES  (BM * A_STRIDE * 2)        // 50176 per plane
#define W_TILE   (128 * W_STRIDE * 2)       // 18432 per plane
#define W_BUF    (2 * W_TILE)               // hi+lo = 36864

#define OFF_A_HI 0
#define OFF_A_LO A_BYTES
#define OFF_W    (2 * A_BYTES)              // 100352
#define OFF_SIDS (OFF_W + 2 * W_BUF)        // 174080
#define OFF_STS  (OFF_SIDS + 256)
#define OFF_BR   (OFF_STS + 256)
#define OFF_BZ   (OFF_BR + 512)
#define OFF_BIN  (OFF_BZ + 512)
#define OFF_BHN  (OFF_BIN + 512)
#define SMEM_TOTAL (OFF_BHN + 512)          // 176640

__device__ __nv_bfloat16 g_whi[G3 * KTOT];  // fused W hi plane [gate][k]
__device__ __nv_bfloat16 g_wlo[G3 * KTOT];  // fused W lo plane

// ------------------------------- helpers -----------------------------------

__device__ __forceinline__ uint32_t smem_u32(const void* p) {
    uint32_t a;
    asm("{ .reg .u64 t; cvta.to.shared.u64 t, %1; cvt.u32.u64 %0, t; }"
        : "=r"(a) : "l"(p));
    return a;
}

#define LDSM_X4(r0, r1, r2, r3, addr) \
    asm volatile("ldmatrix.sync.aligned.m8n8.x4.shared.b16 {%0,%1,%2,%3}, [%4];" \
                 : "=r"(r0), "=r"(r1), "=r"(r2), "=r"(r3) : "r"(addr))

#define MMA_BF16(cp, a, b0, b1) \
    asm volatile("mma.sync.aligned.m16n8k16.row.col.f32.bf16.bf16.f32 " \
                 "{%0,%1,%2,%3}, {%4,%5,%6,%7}, {%8,%9}, {%0,%1,%2,%3};" \
                 : "+f"((cp)[0]), "+f"((cp)[1]), "+f"((cp)[2]), "+f"((cp)[3]) \
                 : "r"((a)[0]), "r"((a)[1]), "r"((a)[2]), "r"((a)[3]), \
                   "r"(b0), "r"(b1))

#define CP_ASYNC16(dst, src) \
    asm volatile("cp.async.cg.shared.global [%0], [%1], 16;" \
                 :: "r"((uint32_t)(dst)), "l"(src) : "memory")
#define CP_COMMIT() asm volatile("cp.async.commit_group;" ::: "memory")
#define CP_WAIT1()  asm volatile("cp.async.wait_group 1;" ::: "memory")
#define CP_WAIT0()  asm volatile("cp.async.wait_group 0;" ::: "memory")

__device__ __forceinline__ float sigmoidf_(float x) {
    return 1.0f / (1.0f + __expf(-x));
}
__device__ __forceinline__ uint32_t bf2_u32(__nv_bfloat162 v) {
    return *reinterpret_cast<uint32_t*>(&v);
}

// ------------------------- weight prep (runs first) -------------------------

__global__ void prep_weights(const float* __restrict__ Wih,
                             const float* __restrict__ Whh) {
    int idx = blockIdx.x * blockDim.x + threadIdx.x;
    if (idx >= G3 * KTOT) return;
    int g = idx / KTOT, k = idx - g * KTOT;
    float w = (k < MSGDIM) ? Wih[(size_t)g * MSGDIM + k]
                           : Whh[(size_t)g * HDIM + (k - MSGDIM)];
    __nv_bfloat16 hb = __float2bfloat16(w);
    __nv_bfloat16 lb = __float2bfloat16(w - __bfloat162float(hb));
    g_whi[idx] = hb;
    g_wlo[idx] = lb;
}

// --------------------------------- main ------------------------------------

extern __shared__ __align__(1024) unsigned char smem_raw[];

__global__ __launch_bounds__(NTHREADS, 1)
void gru_mma_kernel(const float* __restrict__ memory,
                    const int*   __restrict__ ids,
                    const float* __restrict__ msgs,
                    const float* __restrict__ ts,
                    const float* __restrict__ bih,
                    const float* __restrict__ bhh,
                    float* __restrict__ out_mem,
                    float* __restrict__ out_lu,
                    int B)
{
    const int t    = threadIdx.x;
    const int lane = t & 31;
    const int wid  = t >> 5;
    const int m_base = (wid & 1) * 32;     // warp row block (2 x 32 = 64)
    const int n_base = (wid >> 1) * 32;    // warp col block (4 x 32 = 128)
    const int base = blockIdx.x * BM;

    const uint32_t sbase = smem_u32(smem_raw);
    int*   sids_s = (int*)  (smem_raw + OFF_SIDS);
    float* sts_s  = (float*)(smem_raw + OFF_STS);
    float* br_s   = (float*)(smem_raw + OFF_BR);
    float* bz_s   = (float*)(smem_raw + OFF_BZ);
    float* bin_s  = (float*)(smem_raw + OFF_BIN);
    float* bhn_s  = (float*)(smem_raw + OFF_BHN);

    if (t < BM) {
        int g = base + t;
        sids_s[t] = (g < B) ? ids[g] : 0;
        sts_s[t]  = (g < B) ? ts[g]  : 0.0f;
    }
    if (t < 128) {
        br_s[t]  = bih[t]       + bhh[t];
        bz_s[t]  = bih[128 + t] + bhh[128 + t];
        bin_s[t] = bih[256 + t];
        bhn_s[t] = bhh[256 + t];
    }
    __syncthreads();

    // ---- stage A = [X | H] rows as bf16 hi/lo planes (row-major, padded) ----
    {
        unsigned char* ahi = smem_raw + OFF_A_HI;
        unsigned char* alo = smem_raw + OFF_A_LO;
        #pragma unroll
        for (int j = 0; j < (BM * (KTOT / 4)) / NTHREADS; ++j) {  // 24 iters
            int idx = t + j * NTHREADS;
            int row = idx / 96, c4 = idx % 96;                    // c4: float4 idx
            float4 v;
            if (c4 < 64) {
                int g = base + row; if (g >= B) g = B - 1;
                v = *(const float4*)(msgs + (size_t)g * MSGDIM + c4 * 4);
            } else {
                v = *(const float4*)(memory + (size_t)sids_s[row] * HDIM
                                     + (c4 - 64) * 4);
            }
            __nv_bfloat162 h01 = __floats2bfloat162_rn(v.x, v.y);
            __nv_bfloat162 h23 = __floats2bfloat162_rn(v.z, v.w);
            __nv_bfloat162 l01 = __floats2bfloat162_rn(v.x - __bfloat162float(h01.x),
                                                       v.y - __bfloat162float(h01.y));
            __nv_bfloat162 l23 = __floats2bfloat162_rn(v.z - __bfloat162float(h23.x),
                                                       v.w - __bfloat162float(h23.y));
            uint32_t off = ((uint32_t)row * A_STRIDE + c4 * 4) * 2;
            *(uint2*)(ahi + off) = make_uint2(bf2_u32(h01), bf2_u32(h23));
            *(uint2*)(alo + off) = make_uint2(bf2_u32(l01), bf2_u32(l23));
        }
    }

    // operand address bases (bytes from plane start)
    const uint32_t aoff0 = (((uint32_t)m_base + (lane & 15)) * A_STRIDE
                            + ((lane >> 4) << 3)) * 2;
    const uint32_t boff0 = (((uint32_t)n_base + ((lane >> 4) << 3) + (lane & 7))
                            * W_STRIDE + (((lane >> 3) & 1) << 3)) * 2;

    float T[2][4][4];   // running GRU state per owned (row, col) element

    #pragma unroll
    for (int blk = 0; blk < 4; ++blk) {
        const int gb = (blk == 0) ? 0 : (blk == 3) ? 128 : 256;
        const int ks = (blk == 1) ? 256 : 0;
        const int ke = (blk == 2) ? 256 : 384;
        const int nch = (ke - ks) >> 6;

        float c[2][4][4];
        #pragma unroll
        for (int i = 0; i < 2; ++i)
            #pragma unroll
            for (int jn = 0; jn < 4; ++jn)
                #pragma unroll
                for (int e = 0; e < 4; ++e) c[i][jn][e] = 0.0f;

        __syncthreads();   // previous block's compute done; W bufs free

        // prologue: chunk 0 into buffer 0
        {
            uint32_t dhi = sbase + OFF_W;
            #pragma unroll
            for (int j = 0; j < 4; ++j) {
                int idx = t + j * NTHREADS;
                int r = idx >> 3, seg = idx & 7;
                size_t so = (size_t)(gb + r) * KTOT + ks + seg * 8;
                CP_ASYNC16(dhi + r * (W_STRIDE * 2) + seg * 16,
                           (const char*)g_whi + so * 2);
                CP_ASYNC16(dhi + W_TILE + r * (W_STRIDE * 2) + seg * 16,
                           (const char*)g_wlo + so * 2);
            }
            CP_COMMIT();
        }

        for (int ch = 0; ch < nch; ++ch) {
            if (ch + 1 < nch) {
                uint32_t dhi = sbase + OFF_W + ((ch + 1) & 1) * W_BUF;
                int kb = ks + (ch + 1) * 64;
                #pragma unroll
                for (int j = 0; j < 4; ++j) {
                    int idx = t + j * NTHREADS;
                    int r = idx >> 3, seg = idx & 7;
                    size_t so = (size_t)(gb + r) * KTOT + kb + seg * 8;
                    CP_ASYNC16(dhi + r * (W_STRIDE * 2) + seg * 16,
                               (const char*)g_whi + so * 2);
                    CP_ASYNC16(dhi + W_TILE + r * (W_STRIDE * 2) + seg * 16,
                               (const char*)g_wlo + so * 2);
                }
                CP_COMMIT();
                CP_WAIT1();
            } else {
                CP_WAIT0();
            }
            __syncthreads();

            const uint32_t whi = sbase + OFF_W + (ch & 1) * W_BUF;
            const uint32_t wlo = whi + W_TILE;
            const int kg = ks + ch * 64;

            #pragma unroll
            for (int s = 0; s < 4; ++s) {
                uint32_t aaddr = sbase + aoff0 + (uint32_t)(kg + s * 16) * 2;
                uint32_t ah0[4], ah1[4], al0[4], al1[4];
                LDSM_X4(ah0[0], ah0[1], ah0[2], ah0[3], aaddr + OFF_A_HI);
                LDSM_X4(ah1[0], ah1[1], ah1[2], ah1[3],
                        aaddr + OFF_A_HI + 16 * A_STRIDE * 2);
                LDSM_X4(al0[0], al0[1], al0[2], al0[3], aaddr + OFF_A_LO);
                LDSM_X4(al1[0], al1[1], al1[2], al1[3],
                        aaddr + OFF_A_LO + 16 * A_STRIDE * 2);

                uint32_t baddr = boff0 + (uint32_t)(s * 16) * 2;
                uint32_t bh0[4], bh1[4], bl0[4], bl1[4];
                LDSM_X4(bh0[0], bh0[1], bh0[2], bh0[3], whi + baddr);
                LDSM_X4(bh1[0], bh1[1], bh1[2], bh1[3],
                        whi + baddr + 16 * W_STRIDE * 2);
                LDSM_X4(bl0[0], bl0[1], bl0[2], bl0[3], wlo + baddr);
                LDSM_X4(bl1[0], bl1[1], bl1[2], bl1[3],
                        wlo + baddr + 16 * W_STRIDE * 2);

                #pragma unroll
                for (int mt = 0; mt < 2; ++mt) {
                    uint32_t* ah = mt ? ah1 : ah0;
                    uint32_t* al = mt ? al1 : al0;
                    #pragma unroll
                    for (int nt = 0; nt < 4; ++nt) {
                        uint32_t* bh = (nt < 2) ? bh0 : bh1;
                        uint32_t* bl = (nt < 2) ? bl0 : bl1;
                        int o = (nt & 1) * 2;
                        float* cp = c[mt][nt];
                        MMA_BF16(cp, ah, bh[o], bh[o + 1]);   // hi * hi
                        MMA_BF16(cp, ah, bl[o], bl[o + 1]);   // hi * lo
                        MMA_BF16(cp, al, bh[o], bh[o + 1]);   // lo * hi
                    }
                }
            }
            __syncthreads();   // compute done before next prefetch overwrites
        }

        // ---- block epilogue (register-resident state) ----
        #pragma unroll
        for (int mt = 0; mt < 2; ++mt) {
            #pragma unroll
            for (int nt = 0; nt < 4; ++nt) {
                int row0 = m_base + mt * 16 + (lane >> 2);
                int colb = n_base + nt * 8 + ((lane & 3) << 1);
                #pragma unroll
                for (int h = 0; h < 2; ++h) {
                    int row = row0 + h * 8;
                    float a0 = c[mt][nt][h * 2 + 0];
                    float a1 = c[mt][nt][h * 2 + 1];
                    float& t0 = T[mt][nt][h * 2 + 0];
                    float& t1 = T[mt][nt][h * 2 + 1];
                    if (blk == 0) {
                        t0 = sigmoidf_(a0 + br_s[colb]);
                        t1 = sigmoidf_(a1 + br_s[colb + 1]);
                    } else if (blk == 1) {
                        t0 = t0 * (a0 + bhn_s[colb]);
                        t1 = t1 * (a1 + bhn_s[colb + 1]);
                    } else if (blk == 2) {
                        t0 = tanhf(a0 + bin_s[colb] + t0);
                        t1 = tanhf(a1 + bin_s[colb + 1] + t1);
                    } else {
                        float z0 = sigmoidf_(a0 + bz_s[colb]);
                        float z1 = sigmoidf_(a1 + bz_s[colb + 1]);
                        if (base + row < B) {
                            int sid = sids_s[row];
                            float2 hv = *(const float2*)(memory
                                          + (size_t)sid * HDIM + colb);
                            float2 o;
                            o.x = (1.0f - z0) * t0 + z0 * hv.x;
                            o.y = (1.0f - z1) * t1 + z1 * hv.y;
                            *(float2*)(out_mem + (size_t)sid * HDIM + colb) = o;
                        }
                    }
                }
            }
        }
    }

    if (t < BM && base + t < B) out_lu[sids_s[t]] = sts_s[t];
}

// ------------------------------- launcher -----------------------------------

extern "C" void kernel_launch(void* const* d_in, const int* in_sizes, int n_in,
                              void* d_out, int out_size)
{
    const float* memory      = (const float*)d_in[0];
    const float* last_update = (const float*)d_in[1];
    const int*   ids         = (const int*)  d_in[2];
    const float* msgs        = (const float*)d_in[3];
    const float* ts          = (const float*)d_in[4];
    const float* Wih         = (const float*)d_in[5];
    const float* Whh         = (const float*)d_in[6];
    const float* bih         = (const float*)d_in[7];
    const float* bhh         = (const float*)d_in[8];

    const int n_mem   = in_sizes[0];
    const int n_nodes = in_sizes[1];
    const int B       = in_sizes[2];

    float* out_mem = (float*)d_out;
    float* out_lu  = out_mem + (size_t)n_mem;

    // clone memory + last_update (graph-capturable D2D)
    cudaMemcpyAsync(out_mem, memory,      (size_t)n_mem   * sizeof(float),
                    cudaMemcpyDeviceToDevice, 0);
    cudaMemcpyAsync(out_lu,  last_update, (size_t)n_nodes * sizeof(float),
                    cudaMemcpyDeviceToDevice, 0);

    // fused/split W image (recomputed every call; stream-ordered)
    prep_weights<<<(G3 * KTOT + 255) / 256, 256>>>(Wih, Whh);

    cudaFuncSetAttribute(gru_mma_kernel,
                         cudaFuncAttributeMaxDynamicSharedMemorySize, SMEM_TOTAL);
    int grid = (B + BM - 1) / BM;
    gru_mma_kernel<<<grid, NTHREADS, SMEM_TOTAL>>>(
        memory, ids, msgs, ts, bih, bhh, out_mem, out_lu, B);
}

// round 14
// speedup vs baseline: 1.9476x; 1.1173x over previous
#include <cuda_runtime.h>
#include <cuda_bf16.h>
#include <cstdint>

// ---------------------------------------------------------------------------
// GRU memory updater via mma.sync (m16n8k16 bf16) split-precision GEMM.
// v2: 512 threads (16 warps, warp tile 16x32), term-outer MMA ordering,
//     clone fused into compute CTAs via node bytemap (no cudaMemcpyAsync).
//
//   Fused A = [X(256) | H(128)] (K = 384), per-CTA M = 64 rows.
//   W fused bf16 hi/lo planes built by prep kernel. 3-term split GEMM.
//   Gate blocks: R -> HN -> IN -> Z with register-resident running state.
// ---------------------------------------------------------------------------

#define HDIM     128
#define MSGDIM   256
#define G3       384
#define KTOT     384
#define BM       64
#define NTHREADS 512

#define A_STRIDE 392            // bf16 per A row (384 + 8 pad)
#define W_STRIDE 72             // bf16 per W row (64 + 8 pad)
#define A_BYTES  (BM * A_STRIDE * 2)        // 50176 per plane
#define W_TILE   (128 * W_STRIDE * 2)       // 18432 per plane
#define W_BUF    (2 * W_TILE)               // hi+lo = 36864

#define OFF_A_HI 0
#define OFF_A_LO A_BYTES
#define OFF_W    (2 * A_BYTES)              // 100352
#define OFF_SIDS (OFF_W + 2 * W_BUF)        // 174080
#define OFF_STS  (OFF_SIDS + 256)
#define OFF_BR   (OFF_STS + 256)
#define OFF_BZ   (OFF_BR + 512)
#define OFF_BIN  (OFF_BZ + 512)
#define OFF_BHN  (OFF_BIN + 512)
#define SMEM_TOTAL (OFF_BHN + 512)          // 176640

__device__ __nv_bfloat16 g_whi[G3 * KTOT];
__device__ __nv_bfloat16 g_wlo[G3 * KTOT];
__device__ unsigned char g_map[1 << 20];    // updated-node bytemap

// ------------------------------- helpers -----------------------------------

__device__ __forceinline__ uint32_t smem_u32(const void* p) {
    uint32_t a;
    asm("{ .reg .u64 t; cvta.to.shared.u64 t, %1; cvt.u32.u64 %0, t; }"
        : "=r"(a) : "l"(p));
    return a;
}

#define LDSM_X4(r0, r1, r2, r3, addr) \
    asm volatile("ldmatrix.sync.aligned.m8n8.x4.shared.b16 {%0,%1,%2,%3}, [%4];" \
                 : "=r"(r0), "=r"(r1), "=r"(r2), "=r"(r3) : "r"(addr))

#define MMA_BF16(cp, a, b0, b1) \
    asm volatile("mma.sync.aligned.m16n8k16.row.col.f32.bf16.bf16.f32 " \
                 "{%0,%1,%2,%3}, {%4,%5,%6,%7}, {%8,%9}, {%0,%1,%2,%3};" \
                 : "+f"((cp)[0]), "+f"((cp)[1]), "+f"((cp)[2]), "+f"((cp)[3]) \
                 : "r"((a)[0]), "r"((a)[1]), "r"((a)[2]), "r"((a)[3]), \
                   "r"(b0), "r"(b1))

#define CP_ASYNC16(dst, src) \
    asm volatile("cp.async.cg.shared.global [%0], [%1], 16;" \
                 :: "r"((uint32_t)(dst)), "l"(src) : "memory")
#define CP_COMMIT() asm volatile("cp.async.commit_group;" ::: "memory")
#define CP_WAIT1()  asm volatile("cp.async.wait_group 1;" ::: "memory")
#define CP_WAIT0()  asm volatile("cp.async.wait_group 0;" ::: "memory")

__device__ __forceinline__ float sigmoidf_(float x) {
    return 1.0f / (1.0f + __expf(-x));
}
__device__ __forceinline__ uint32_t bf2_u32(__nv_bfloat162 v) {
    return *reinterpret_cast<uint32_t*>(&v);
}

// --------------------------- prep kernels -----------------------------------

__global__ void zero_map() {
    ((uint32_t*)g_map)[blockIdx.x * 512 + threadIdx.x] = 0;  // 512x512x4 = 1MB
}
__global__ void mark_map(const int* __restrict__ ids, int B) {
    int i = blockIdx.x * blockDim.x + threadIdx.x;
    if (i < B) g_map[ids[i]] = 1;
}
__global__ void prep_weights(const float* __restrict__ Wih,
                             const float* __restrict__ Whh) {
    int idx = blockIdx.x * blockDim.x + threadIdx.x;
    if (idx >= G3 * KTOT) return;
    int g = idx / KTOT, k = idx - g * KTOT;
    float w = (k < MSGDIM) ? Wih[(size_t)g * MSGDIM + k]
                           : Whh[(size_t)g * HDIM + (k - MSGDIM)];
    __nv_bfloat16 hb = __float2bfloat16(w);
    __nv_bfloat16 lb = __float2bfloat16(w - __bfloat162float(hb));
    g_whi[idx] = hb;
    g_wlo[idx] = lb;
}

// --------------------------------- main ------------------------------------

extern __shared__ __align__(1024) unsigned char smem_raw[];

__global__ __launch_bounds__(NTHREADS, 1)
void gru_mma_kernel(const float* __restrict__ memory,
                    const float* __restrict__ last_update,
                    const int*   __restrict__ ids,
                    const float* __restrict__ msgs,
                    const float* __restrict__ ts,
                    const float* __restrict__ bih,
                    const float* __restrict__ bhh,
                    float* __restrict__ out_mem,
                    float* __restrict__ out_lu,
                    int B, int n_nodes, int rows_per_cta)
{
    const int t    = threadIdx.x;
    const int lane = t & 31;
    const int wid  = t >> 5;
    const int m_base = (wid & 3) * 16;     // 4 m-blocks of 16 = 64
    const int n_base = (wid >> 2) * 32;    // 4 n-blocks of 32 = 128
    const int base = blockIdx.x * BM;

    const uint32_t sbase = smem_u32(smem_raw);
    int*   sids_s = (int*)  (smem_raw + OFF_SIDS);
    float* sts_s  = (float*)(smem_raw + OFF_STS);
    float* br_s   = (float*)(smem_raw + OFF_BR);
    float* bz_s   = (float*)(smem_raw + OFF_BZ);
    float* bin_s  = (float*)(smem_raw + OFF_BIN);
    float* bhn_s  = (float*)(smem_raw + OFF_BHN);

    if (t < BM) {
        int g = base + t;
        sids_s[t] = (g < B) ? ids[g] : 0;
        sts_s[t]  = (g < B) ? ts[g]  : 0.0f;
    }
    if (t < 128) {
        br_s[t]  = bih[t]       + bhh[t];
        bz_s[t]  = bih[128 + t] + bhh[128 + t];
        bin_s[t] = bih[256 + t];
        bhn_s[t] = bhh[256 + t];
    }
    __syncthreads();

    // ---- stage A = [X | H] rows as bf16 hi/lo planes ----
    {
        unsigned char* ahi = smem_raw + OFF_A_HI;
        unsigned char* alo = smem_raw + OFF_A_LO;
        #pragma unroll
        for (int j = 0; j < (BM * (KTOT / 4)) / NTHREADS; ++j) {  // 12 iters
            int idx = t + j * NTHREADS;
            int row = idx / 96, c4 = idx % 96;
            float4 v;
            if (c4 < 64) {
                int g = base + row; if (g >= B) g = B - 1;
                v = *(const float4*)(msgs + (size_t)g * MSGDIM + c4 * 4);
            } else {
                v = *(const float4*)(memory + (size_t)sids_s[row] * HDIM
                                     + (c4 - 64) * 4);
            }
            __nv_bfloat162 h01 = __floats2bfloat162_rn(v.x, v.y);
            __nv_bfloat162 h23 = __floats2bfloat162_rn(v.z, v.w);
            __nv_bfloat162 l01 = __floats2bfloat162_rn(v.x - __bfloat162float(h01.x),
                                                       v.y - __bfloat162float(h01.y));
            __nv_bfloat162 l23 = __floats2bfloat162_rn(v.z - __bfloat162float(h23.x),
                                                       v.w - __bfloat162float(h23.y));
            uint32_t off = ((uint32_t)row * A_STRIDE + c4 * 4) * 2;
            *(uint2*)(ahi + off) = make_uint2(bf2_u32(h01), bf2_u32(h23));
            *(uint2*)(alo + off) = make_uint2(bf2_u32(l01), bf2_u32(l23));
        }
    }

    const uint32_t aoff0 = (((uint32_t)m_base + (lane & 15)) * A_STRIDE
                            + ((lane >> 4) << 3)) * 2;
    const uint32_t boff0 = (((uint32_t)n_base + ((lane >> 4) << 3) + (lane & 7))
                            * W_STRIDE + (((lane >> 3) & 1) << 3)) * 2;

    float T[4][4];   // running GRU state (4 n-tiles x 4 elems)

    #pragma unroll
    for (int blk = 0; blk < 4; ++blk) {
        const int gb = (blk == 0) ? 0 : (blk == 3) ? 128 : 256;
        const int ks = (blk == 1) ? 256 : 0;
        const int ke = (blk == 2) ? 256 : 384;
        const int nch = (ke - ks) >> 6;

        float c[4][4];
        #pragma unroll
        for (int jn = 0; jn < 4; ++jn)
            #pragma unroll
            for (int e = 0; e < 4; ++e) c[jn][e] = 0.0f;

        __syncthreads();   // previous block's compute done; W bufs free

        {   // prologue: chunk 0 into buffer 0
            uint32_t dhi = sbase + OFF_W;
            #pragma unroll
            for (int j = 0; j < 2; ++j) {
                int idx = t + j * NTHREADS;
                int r = idx >> 3, seg = idx & 7;
                size_t so = (size_t)(gb + r) * KTOT + ks + seg * 8;
                CP_ASYNC16(dhi + r * (W_STRIDE * 2) + seg * 16,
                           (const char*)g_whi + so * 2);
                CP_ASYNC16(dhi + W_TILE + r * (W_STRIDE * 2) + seg * 16,
                           (const char*)g_wlo + so * 2);
            }
            CP_COMMIT();
        }

        for (int ch = 0; ch < nch; ++ch) {
            if (ch + 1 < nch) {
                uint32_t dhi = sbase + OFF_W + ((ch + 1) & 1) * W_BUF;
                int kb = ks + (ch + 1) * 64;
                #pragma unroll
                for (int j = 0; j < 2; ++j) {
                    int idx = t + j * NTHREADS;
                    int r = idx >> 3, seg = idx & 7;
                    size_t so = (size_t)(gb + r) * KTOT + kb + seg * 8;
                    CP_ASYNC16(dhi + r * (W_STRIDE * 2) + seg * 16,
                               (const char*)g_whi + so * 2);
                    CP_ASYNC16(dhi + W_TILE + r * (W_STRIDE * 2) + seg * 16,
                               (const char*)g_wlo + so * 2);
                }
                CP_COMMIT();
                CP_WAIT1();
            } else {
                CP_WAIT0();
            }
            __syncthreads();

            const uint32_t whi = sbase + OFF_W + (ch & 1) * W_BUF;
            const uint32_t wlo = whi + W_TILE;
            const int kg = ks + ch * 64;

            #pragma unroll
            for (int s = 0; s < 4; ++s) {
                uint32_t aaddr = sbase + aoff0 + (uint32_t)(kg + s * 16) * 2;
                uint32_t ah[4], al[4];
                LDSM_X4(ah[0], ah[1], ah[2], ah[3], aaddr + OFF_A_HI);
                LDSM_X4(al[0], al[1], al[2], al[3], aaddr + OFF_A_LO);

                uint32_t baddr = boff0 + (uint32_t)(s * 16) * 2;
                uint32_t bh0[4], bh1[4], bl0[4], bl1[4];
                LDSM_X4(bh0[0], bh0[1], bh0[2], bh0[3], whi + baddr);
                LDSM_X4(bh1[0], bh1[1], bh1[2], bh1[3],
                        whi + baddr + 16 * W_STRIDE * 2);
                LDSM_X4(bl0[0], bl0[1], bl0[2], bl0[3], wlo + baddr);
                LDSM_X4(bl1[0], bl1[1], bl1[2], bl1[3],
                        wlo + baddr + 16 * W_STRIDE * 2);

                // term-outer: same-acc reuse separated by 4 independent tiles
                #pragma unroll
                for (int term = 0; term < 3; ++term) {
                    uint32_t* a = (term == 2) ? al : ah;
                    #pragma unroll
                    for (int nt = 0; nt < 4; ++nt) {
                        uint32_t* b = (term == 1) ? ((nt < 2) ? bl0 : bl1)
                                                  : ((nt < 2) ? bh0 : bh1);
                        int o = (nt & 1) * 2;
                        MMA_BF16(c[nt], a, b[o], b[o + 1]);
                    }
                }
            }
            __syncthreads();   // compute done before next prefetch overwrites
        }

        // ---- block epilogue (register-resident state) ----
        #pragma unroll
        for (int nt = 0; nt < 4; ++nt) {
            int row0 = m_base + (lane >> 2);
            int colb = n_base + nt * 8 + ((lane & 3) << 1);
            #pragma unroll
            for (int h = 0; h < 2; ++h) {
                int row = row0 + h * 8;
                float a0 = c[nt][h * 2 + 0];
                float a1 = c[nt][h * 2 + 1];
                float& t0 = T[nt][h * 2 + 0];
                float& t1 = T[nt][h * 2 + 1];
                if (blk == 0) {
                    t0 = sigmoidf_(a0 + br_s[colb]);
                    t1 = sigmoidf_(a1 + br_s[colb + 1]);
                } else if (blk == 1) {
                    t0 = t0 * (a0 + bhn_s[colb]);
                    t1 = t1 * (a1 + bhn_s[colb + 1]);
                } else if (blk == 2) {
                    t0 = tanhf(a0 + bin_s[colb] + t0);
                    t1 = tanhf(a1 + bin_s[colb + 1] + t1);
                } else {
                    float z0 = sigmoidf_(a0 + bz_s[colb]);
                    float z1 = sigmoidf_(a1 + bz_s[colb + 1]);
                    if (base + row < B) {
                        int sid = sids_s[row];
                        float2 hv = *(const float2*)(memory
                                      + (size_t)sid * HDIM + colb);
                        float2 o;
                        o.x = (1.0f - z0) * t0 + z0 * hv.x;
                        o.y = (1.0f - z1) * t1 + z1 * hv.y;
                        *(float2*)(out_mem + (size_t)sid * HDIM + colb) = o;
                    }
                }
            }
        }
    }

    if (t < BM && base + t < B) out_lu[sids_s[t]] = sts_s[t];

    // ---- fused clone: copy this CTA's slice of non-updated rows ----
    {
        int r0 = blockIdx.x * rows_per_cta;
        // memory rows: one warp per row, one float4 per lane (512B/row)
        for (int rr = wid; rr < rows_per_cta; rr += 16) {
            int row = r0 + rr;
            if (row < n_nodes && g_map[row] == 0) {
                const float4* src = (const float4*)(memory + (size_t)row * HDIM);
                float4*       dst = (float4*)(out_mem + (size_t)row * HDIM);
                dst[lane] = src[lane];
            }
        }
        // last_update
        for (int i = t; i < rows_per_cta; i += NTHREADS) {
            int node = r0 + i;
            if (node < n_nodes && g_map[node] == 0)
                out_lu[node] = last_update[node];
        }
    }
}

// ------------------------------- launcher -----------------------------------

extern "C" void kernel_launch(void* const* d_in, const int* in_sizes, int n_in,
                              void* d_out, int out_size)
{
    const float* memory      = (const float*)d_in[0];
    const float* last_update = (const float*)d_in[1];
    const int*   ids         = (const int*)  d_in[2];
    const float* msgs        = (const float*)d_in[3];
    const float* ts          = (const float*)d_in[4];
    const float* Wih         = (const float*)d_in[5];
    const float* Whh         = (const float*)d_in[6];
    const float* bih         = (const float*)d_in[7];
    const float* bhh         = (const float*)d_in[8];

    const int n_mem   = in_sizes[0];
    const int n_nodes = in_sizes[1];
    const int B       = in_sizes[2];

    float* out_mem = (float*)d_out;
    float* out_lu  = out_mem + (size_t)n_mem;

    // bytemap of updated nodes (zero -> mark), then W image
    zero_map<<<512, 512>>>();
    mark_map<<<(B + 511) / 512, 512>>>(ids, B);
    prep_weights<<<(G3 * KTOT + 255) / 256, 256>>>(Wih, Whh);

    cudaFuncSetAttribute(gru_mma_kernel,
                         cudaFuncAttributeMaxDynamicSharedMemorySize, SMEM_TOTAL);
    int grid = (B + BM - 1) / BM;
    int rows_per_cta = (n_nodes + grid - 1) / grid;
    gru_mma_kernel<<<grid, NTHREADS, SMEM_TOTAL>>>(
        memory, last_update, ids, msgs, ts, bih, bhh,
        out_mem, out_lu, B, n_nodes, rows_per_cta);
}